// round 13
// baseline (speedup 1.0000x reference)
#include <cuda_runtime.h>
#include <cuda_bf16.h>
#include <mma.h>
#include <cstdint>

using namespace nvcuda;

#define TT   512
#define NB   64
#define IN0  256
#define HID  256
#define GATES 1024
#define OC   512   // 2*HID

// ---------------- scratch (static device memory; no allocation) ----------------
__device__ float g_wi_f[(size_t)TT * NB * GATES];  // 128 MB
__device__ float g_wi_b[(size_t)TT * NB * GATES];  // 128 MB
__device__ float g_x1 [(size_t)TT * NB * OC];      // 64 MB (layer-0 out / layer-1 in)
__device__ float g_hbuf[2][2][HID * NB];           // [dir][slot][j*64 + b]
__device__ unsigned int g_ctr[2][8];               // [dir][group] step barrier counters
__device__ int g_len[NB];                          // normalized lengths (int32)

// bf16 2-way split planes (A shared across layers; W holds both dirs back-to-back)
__device__ __nv_bfloat16 g_Ah[(size_t)32768 * 512];
__device__ __nv_bfloat16 g_Am[(size_t)32768 * 512];
__device__ __nv_bfloat16 g_Wh[2 * 512 * 1024];
__device__ __nv_bfloat16 g_Wm[2 * 512 * 1024];

__device__ __forceinline__ uint32_t smem_u32(const void* p) {
    uint32_t a;
    asm("{ .reg .u64 t; cvta.to.shared.u64 t, %1; cvt.u32.u64 %0, t; }" : "=r"(a) : "l"(p));
    return a;
}
__device__ __forceinline__ void cp_async16(uint32_t dst, const void* src) {
    asm volatile("cp.async.cg.shared.global [%0], [%1], 16;" :: "r"(dst), "l"(src));
}
__device__ __forceinline__ void atom_add_release(unsigned int* p, unsigned int v) {
    unsigned int old;
    asm volatile("atom.global.add.release.gpu.u32 %0, [%1], %2;"
                 : "=r"(old) : "l"(p), "r"(v) : "memory");
}
__device__ __forceinline__ unsigned int ld_acquire(const unsigned int* p) {
    unsigned int v;
    asm volatile("ld.global.acquire.gpu.u32 %0, [%1];" : "=r"(v) : "l"(p) : "memory");
    return v;
}

// ---------------- fp32 -> (hi, mid) bf16 split ----------------
__global__ void split2(const float* __restrict__ x,
                       __nv_bfloat16* __restrict__ hi,
                       __nv_bfloat16* __restrict__ mid, int n)
{
    for (int i = blockIdx.x * blockDim.x + threadIdx.x; i < n; i += gridDim.x * blockDim.x) {
        float v = x[i];
        __nv_bfloat16 h = __float2bfloat16(v);
        hi[i] = h;
        mid[i] = __float2bfloat16(v - __bfloat162float(h));
    }
}

// W split (both dirs packed) + hbuf/ctr reset + lengths dtype normalization.
// JAX with x64 disabled silently makes .astype(int64) produce int32; detect width.
__global__ void split2W(const float* __restrict__ Wf, const float* __restrict__ Wb,
                        __nv_bfloat16* __restrict__ hi,
                        __nv_bfloat16* __restrict__ mid, int n,
                        const int* __restrict__ lraw)
{
    int gtid = blockIdx.x * blockDim.x + threadIdx.x;
    if (gtid < 2 * 2 * HID * NB) ((float*)g_hbuf)[gtid] = 0.f;
    if (gtid < 16) ((unsigned int*)g_ctr)[gtid] = 0u;
    if (blockIdx.x == 0) {
        __shared__ int is64;
        if (threadIdx.x == 0) {
            int az = 1;
            for (int i = 1; i < 64; i += 2)
                if (lraw[i] != 0) az = 0;
            is64 = az;
        }
        __syncthreads();
        if (threadIdx.x < NB)
            g_len[threadIdx.x] = is64 ? lraw[2 * threadIdx.x] : lraw[threadIdx.x];
    }
    int total = 2 * n;
    for (int i = gtid; i < total; i += gridDim.x * blockDim.x) {
        float v = (i < n) ? Wf[i] : Wb[i - n];
        __nv_bfloat16 h = __float2bfloat16(v);
        hi[i] = h;
        mid[i] = __float2bfloat16(v - __bfloat162float(h));
    }
}

// ---------------- bf16 HMMA GEMM (2-way split, 3 products: hh, hm, mh) ----------------
#define LDAS 40
#define LDBS 136
#define PLANE_A (128 * LDAS * 2)          // 10240 B
#define PLANE_B (32 * LDBS * 2)           // 8704 B
#define ABUF (2 * PLANE_A)
#define BBUF (2 * PLANE_B)
#define BUFB (ABUF + BBUF)                // 37888 B
#define GEMM_SM_BYTES (2 * BUFB)          // 75776 B (>= epilogue 67584)

__global__ __launch_bounds__(256) void bf16_gemm_bias(
    const __nv_bfloat16* __restrict__ Ah, const __nv_bfloat16* __restrict__ Am,
    const __nv_bfloat16* __restrict__ Wh, const __nv_bfloat16* __restrict__ Wm,
    const float* __restrict__ bf, float* __restrict__ Cf,
    const float* __restrict__ bb, float* __restrict__ Cb,
    int K)
{
    extern __shared__ char sm[];
    const uint32_t smb = smem_u32(sm);
    const int tid = threadIdx.x;
    const int wid = tid >> 5;
    const int warpM = wid & 3;
    const int warpN = wid >> 2;
    const int n0 = blockIdx.x * 128;
    const int m0 = blockIdx.y * 128;
    const size_t zoff = (size_t)blockIdx.z * K * GATES;

    const float* bias = blockIdx.z ? bb : bf;
    float*       C    = blockIdx.z ? Cb : Cf;

    const __nv_bfloat16* APs[2] = {Ah, Am};
    const __nv_bfloat16* WPs[2] = {Wh, Wm};

    wmma::fragment<wmma::accumulator, 16, 16, 16, float> acc[2][4];
#pragma unroll
    for (int i = 0; i < 2; i++)
#pragma unroll
        for (int j = 0; j < 4; j++) wmma::fill_fragment(acc[i][j], 0.0f);

    const int nchunks = K >> 5;

    auto stage = [&](int buf, int c) {
        const int kb = c << 5;
        const uint32_t base = smb + buf * BUFB;
#pragma unroll
        for (int i = 0; i < 4; i++) {
            int idx = tid + (i << 8);
            int plane = idx >> 9, r = idx & 511;
            int row = r >> 2, q = r & 3;
            cp_async16(base + plane * PLANE_A + (row * LDAS + (q << 3)) * 2,
                       APs[plane] + (size_t)(m0 + row) * K + kb + (q << 3));
        }
#pragma unroll
        for (int i = 0; i < 4; i++) {
            int idx = tid + (i << 8);
            int plane = idx >> 9, r = idx & 511;
            int row = r >> 4, q = r & 15;
            cp_async16(base + ABUF + plane * PLANE_B + (row * LDBS + (q << 3)) * 2,
                       WPs[plane] + zoff + (size_t)(kb + row) * GATES + n0 + (q << 3));
        }
        asm volatile("cp.async.commit_group;" ::: "memory");
    };

    stage(0, 0);

    for (int c = 0; c < nchunks; c++) {
        if (c + 1 < nchunks) {
            stage((c + 1) & 1, c + 1);
            asm volatile("cp.async.wait_group 1;" ::: "memory");
        } else {
            asm volatile("cp.async.wait_group 0;" ::: "memory");
        }
        __syncthreads();

        const char* bufp = sm + (c & 1) * BUFB;
#pragma unroll
        for (int ks = 0; ks < 2; ks++) {
            wmma::fragment<wmma::matrix_a, 16, 16, 16, __nv_bfloat16, wmma::row_major> af[2][2];
#pragma unroll
            for (int pa = 0; pa < 2; pa++) {
                const __nv_bfloat16* sA = (const __nv_bfloat16*)(bufp + pa * PLANE_A)
                                          + (warpM * 32) * LDAS + ks * 16;
                wmma::load_matrix_sync(af[pa][0], sA, LDAS);
                wmma::load_matrix_sync(af[pa][1], sA + 16 * LDAS, LDAS);
            }
#pragma unroll
            for (int pb = 0; pb < 2; pb++) {
                const __nv_bfloat16* sB = (const __nv_bfloat16*)(bufp + ABUF + pb * PLANE_B)
                                          + (ks * 16) * LDBS + warpN * 64;
                wmma::fragment<wmma::matrix_b, 16, 16, 16, __nv_bfloat16, wmma::row_major> bfr[4];
#pragma unroll
                for (int j = 0; j < 4; j++)
                    wmma::load_matrix_sync(bfr[j], sB + j * 16, LDBS);
#pragma unroll
                for (int pa = 0; pa < 2; pa++) {
                    if (pa == 1 && pb == 1) continue;   // drop mid*mid (~2^-34)
#pragma unroll
                    for (int i = 0; i < 2; i++)
#pragma unroll
                        for (int j = 0; j < 4; j++)
                            wmma::mma_sync(acc[i][j], af[pa][i], bfr[j], acc[i][j]);
                }
            }
        }
        __syncthreads();
    }

#define LDE 132
    float* sE = (float*)sm;
#pragma unroll
    for (int i = 0; i < 2; i++)
#pragma unroll
        for (int j = 0; j < 4; j++)
            wmma::store_matrix_sync(sE + (warpM * 32 + i * 16) * LDE + warpN * 64 + j * 16,
                                    acc[i][j], LDE, wmma::mem_row_major);
    __syncthreads();

#pragma unroll
    for (int i = 0; i < 16; i++) {
        int idx = tid + (i << 8);
        int row = idx >> 5, q = idx & 31;
        const float4 bv = *(const float4*)(bias + n0 + (q << 2));
        const float* e = sE + row * LDE + (q << 2);
        float4 v = make_float4(e[0] + bv.x, e[1] + bv.y, e[2] + bv.z, e[3] + bv.w);
        *(float4*)(C + (size_t)(m0 + row) * GATES + n0 + (q << 2)) = v;
    }
}

// ---------------- recurrent kernel: dual-direction interleaved HMMA ----------------
// grid = 64 CTAs: group(4, 16 batches each) x ci(16, 16 cells / 64 gate-cols each).
// Both directions' Whh slices resident as bf16 hi/mid planes (4 x 256x64).
// Per iteration: fwd phase then bwd phase; separate counters per dir so each
// barrier wait is "aged" by the opposite direction's compute -> near-zero spin.
// 16 real batches fill the wmma m16 dimension (no zero-row waste).
#define RW_LD 72           // weight plane ld (bf16)
#define RH_LD 264          // h plane ld (bf16)
#define SG_LD 72
#define R_WPL (256 * RW_LD * 2)                  // 36864 B per plane
#define R_W(d, p) ((2 * (d) + (p)) * R_WPL)      // 4 planes: 147456 B
#define R_SHH (4 * R_WPL)                        // 147456
#define R_SHM (R_SHH + 16 * RH_LD * 2)           // +8448
#define R_SG  (R_SHM + 16 * RH_LD * 2)           // 164352
#define REC_SM_BYTES (R_SG + 2 * 16 * SG_LD * 4) // 173568

__device__ __forceinline__ float sigm(float x) { return 1.f / (1.f + expf(-x)); }

__global__ __launch_bounds__(256) void lstm_layer(
    const float* __restrict__ wi_f, const float* __restrict__ wi_b,
    const float* __restrict__ Whh_f, const float* __restrict__ Whh_b,
    float* __restrict__ outbuf,        // [TT][NB][OC]
    float* __restrict__ hn, float* __restrict__ cn)   // [2][NB][HID] (this layer)
{
    extern __shared__ char smraw[];
    __nv_bfloat16* sHh = (__nv_bfloat16*)(smraw + R_SHH);
    __nv_bfloat16* sHm = (__nv_bfloat16*)(smraw + R_SHM);
    float*         sG  = (float*)(smraw + R_SG);

    const int group = blockIdx.x >> 4;   // 0..3, 16 batches
    const int ci    = blockIdx.x & 15;   // 0..15, cells [ci*16, ci*16+16)
    const int b0    = group << 4;
    const int tid   = threadIdx.x;
    const int warp  = tid >> 5;
    const int ntile = warp & 3;          // 16-col tile within our 64 cols
    const int khalf = warp >> 2;         // k range half

    // resident weight slices for BOTH directions, split to bf16 hi/mid
#pragma unroll
    for (int dir = 0; dir < 2; dir++) {
        const float* Whh = dir ? Whh_b : Whh_f;
        __nv_bfloat16* wh = (__nv_bfloat16*)(smraw + R_W(dir, 0));
        __nv_bfloat16* wm = (__nv_bfloat16*)(smraw + R_W(dir, 1));
        for (int idx = tid; idx < 16384; idx += 256) {
            int k = idx >> 6, cc = idx & 63;
            int gc = ((cc >> 4) << 8) + (ci << 4) + (cc & 15);
            float v = __ldg(Whh + (size_t)k * GATES + gc);
            __nv_bfloat16 h = __float2bfloat16(v);
            wh[k * RW_LD + cc] = h;
            wm[k * RW_LD + cc] = __float2bfloat16(v - __bfloat162float(h));
        }
    }

    // cell ownership: thread owns cell (cj, cb) for both dirs
    const int cb = tid >> 4;             // 0..15 batch
    const int cj = tid & 15;             // cell col within our 16
    const int clen = g_len[b0 + cb];
    float cS[2] = {0.f, 0.f}, hS[2] = {0.f, 0.f};

    __syncthreads();

    for (int s = 0; s < TT; s++) {
#pragma unroll
        for (int dir = 0; dir < 2; dir++) {
            const int t = dir ? (TT - 1 - s) : s;

            // hoist wi loads for own cell's 4 gates (overlap with barrier wait)
            const float* wrow = (dir ? wi_b : wi_f)
                              + ((size_t)t * NB + b0 + cb) * GATES + (ci << 4) + cj;
            float w0 = __ldg(wrow + 0);
            float w1 = __ldg(wrow + 256);
            float w2 = __ldg(wrow + 512);
            float w3 = __ldg(wrow + 768);

            // wait for peers' h(s) of this direction (aged by other dir's phase)
            if (tid == 0 && s > 0) {
                unsigned int target = (unsigned int)(s << 4);
                while (ld_acquire(&g_ctr[dir][group]) < target) __nanosleep(32);
            }
            __syncthreads();

            // gather h tile (256 j x 16 b) from L2, split to bf16 planes [b][k]
            const float* hb = g_hbuf[dir][s & 1];
#pragma unroll
            for (int i = 0; i < 16; i++) {
                int idx = tid + (i << 8);
                int j = idx >> 4, b = idx & 15;
                float v = __ldcg(hb + (j << 6) + b0 + b);
                __nv_bfloat16 h = __float2bfloat16(v);
                sHh[b * RH_LD + j] = h;
                sHm[b * RH_LD + j] = __float2bfloat16(v - __bfloat162float(h));
            }
            __syncthreads();

            // gates = h @ Whh via HMMA: warp -> n-tile ntile, k-half khalf
            {
                const __nv_bfloat16* wh = (__nv_bfloat16*)(smraw + R_W(dir, 0));
                const __nv_bfloat16* wm = (__nv_bfloat16*)(smraw + R_W(dir, 1));
                wmma::fragment<wmma::accumulator, 16, 16, 16, float> acc;
                wmma::fill_fragment(acc, 0.0f);
#pragma unroll
                for (int q = 0; q < 8; q++) {
                    int kt = (khalf << 3) + q;
                    wmma::fragment<wmma::matrix_a, 16, 16, 16, __nv_bfloat16, wmma::row_major> ah, am;
                    wmma::fragment<wmma::matrix_b, 16, 16, 16, __nv_bfloat16, wmma::row_major> bh, bm;
                    wmma::load_matrix_sync(ah, sHh + kt * 16, RH_LD);
                    wmma::load_matrix_sync(am, sHm + kt * 16, RH_LD);
                    wmma::load_matrix_sync(bh, wh + (kt * 16) * RW_LD + ntile * 16, RW_LD);
                    wmma::load_matrix_sync(bm, wm + (kt * 16) * RW_LD + ntile * 16, RW_LD);
                    wmma::mma_sync(acc, ah, bh, acc);
                    wmma::mma_sync(acc, ah, bm, acc);
                    wmma::mma_sync(acc, am, bh, acc);
                }
                wmma::store_matrix_sync(sG + khalf * (16 * SG_LD) + ntile * 16,
                                        acc, SG_LD, wmma::mem_row_major);
            }
            __syncthreads();

            {   // cell update: sum the two k-half partials; one cell per thread
                const float* g0 = sG + cb * SG_LD;
                const float* g1 = g0 + 16 * SG_LD;
                float gi = g0[cj]      + g1[cj]      + w0;
                float gf = g0[16 + cj] + g1[16 + cj] + w1;
                float go = g0[32 + cj] + g1[32 + cj] + w2;
                float gc = g0[48 + cj] + g1[48 + cj] + w3;
                float cN = sigm(gf + 1.f) * cS[dir] + sigm(gi) * tanhf(gc);
                float hN = sigm(go) * tanhf(cN);
                float ov = 0.f;
                if (t < clen) { cS[dir] = cN; hS[dir] = hN; ov = hN; }
                outbuf[((size_t)s * NB + b0 + cb) * OC + (dir << 8) + (ci << 4) + cj] = ov;
                __stcg(&g_hbuf[dir][(s + 1) & 1][(((ci << 4) + cj) << 6) + b0 + cb], hS[dir]);
            }

            __syncthreads();
            if (tid == 0) atom_add_release(&g_ctr[dir][group], 1u);
        }
    }

#pragma unroll
    for (int dir = 0; dir < 2; dir++) {
        hn[((size_t)dir * NB + b0 + cb) * HID + (ci << 4) + cj] = hS[dir];
        cn[((size_t)dir * NB + b0 + cb) * HID + (ci << 4) + cj] = cS[dir];
    }
}

// ---------------- launcher ----------------
extern "C" void kernel_launch(void* const* d_in, const int* in_sizes, int n_in,
                              void* d_out, int out_size)
{
    const float* inputs  = (const float*)d_in[0];
    const int*   lengths = (const int*)d_in[1];   // width auto-detected on device
    const float* Wih_f0 = (const float*)d_in[2];
    const float* Whh_f0 = (const float*)d_in[3];
    const float* b_f0   = (const float*)d_in[4];
    const float* Wih_b0 = (const float*)d_in[5];
    const float* Whh_b0 = (const float*)d_in[6];
    const float* b_b0   = (const float*)d_in[7];
    const float* Wih_f1 = (const float*)d_in[8];
    const float* Whh_f1 = (const float*)d_in[9];
    const float* b_f1   = (const float*)d_in[10];
    const float* Wih_b1 = (const float*)d_in[11];
    const float* Whh_b1 = (const float*)d_in[12];
    const float* b_b1   = (const float*)d_in[13];
    float* out = (float*)d_out;

    float *wi_f, *wi_b, *x1;
    __nv_bfloat16 *Ah, *Am, *Wh, *Wm;
    cudaGetSymbolAddress((void**)&wi_f, g_wi_f);
    cudaGetSymbolAddress((void**)&wi_b, g_wi_b);
    cudaGetSymbolAddress((void**)&x1,  g_x1);
    cudaGetSymbolAddress((void**)&Ah, g_Ah);
    cudaGetSymbolAddress((void**)&Am, g_Am);
    cudaGetSymbolAddress((void**)&Wh, g_Wh);
    cudaGetSymbolAddress((void**)&Wm, g_Wm);

    cudaFuncSetAttribute(lstm_layer, cudaFuncAttributeMaxDynamicSharedMemorySize, REC_SM_BYTES);
    cudaFuncSetAttribute(bf16_gemm_bias, cudaFuncAttributeMaxDynamicSharedMemorySize, GEMM_SM_BYTES);

    float* hn0 = out + (size_t)TT * NB * OC;          // hn: (4, B, H)
    float* cn0 = hn0 + 4 * NB * HID;                  // cn: (4, B, H)

    dim3 gGrid(8, 256, 2);   // N tiles x M tiles x direction

    // ---- layer 0 (slot #4 = lstm_layer for ncu) ----
    split2<<<1024, 256>>>(inputs, Ah, Am, TT * NB * IN0);                   // 1
    split2W<<<256, 256>>>(Wih_f0, Wih_b0, Wh, Wm, IN0 * GATES, lengths);    // 2 (+reset)
    bf16_gemm_bias<<<gGrid, 256, GEMM_SM_BYTES>>>(Ah, Am, Wh, Wm,           // 3
                                                  b_f0, wi_f, b_b0, wi_b, IN0);
    lstm_layer<<<64, 256, REC_SM_BYTES>>>(wi_f, wi_b, Whh_f0, Whh_b0, x1,   // 4
                                          hn0, cn0);

    // ---- layer 1 ----
    split2<<<1024, 256>>>(x1, Ah, Am, TT * NB * OC);
    split2W<<<512, 256>>>(Wih_f1, Wih_b1, Wh, Wm, OC * GATES, lengths);     // re-resets hbuf/ctr
    bf16_gemm_bias<<<gGrid, 256, GEMM_SM_BYTES>>>(Ah, Am, Wh, Wm,
                                                  b_f1, wi_f, b_b1, wi_b, OC);
    lstm_layer<<<64, 256, REC_SM_BYTES>>>(wi_f, wi_b, Whh_f1, Whh_b1, out,
                                          hn0 + 2 * NB * HID, cn0 + 2 * NB * HID);
}

// round 14
// speedup vs baseline: 1.4529x; 1.4529x over previous
#include <cuda_runtime.h>
#include <cuda_bf16.h>
#include <mma.h>
#include <cstdint>

using namespace nvcuda;

#define TT   512
#define NB   64
#define IN0  256
#define HID  256
#define GATES 1024
#define OC   512   // 2*HID

// ---------------- scratch (static device memory; no allocation) ----------------
__device__ float g_wi_f[(size_t)TT * NB * GATES];  // 128 MB
__device__ float g_wi_b[(size_t)TT * NB * GATES];  // 128 MB
__device__ float g_x1 [(size_t)TT * NB * OC];      // 64 MB (layer-0 out / layer-1 in)
__device__ float g_hbuf[2][2][NB * HID];           // [dir][slot][b*256 + j]  (b-major!)
__device__ unsigned int g_ctr[2][8];               // [dir][btile] step barrier counters
__device__ int g_len[NB];                          // normalized lengths (int32)

// bf16 2-way split planes (A shared across layers; W holds both dirs back-to-back)
__device__ __nv_bfloat16 g_Ah[(size_t)32768 * 512];
__device__ __nv_bfloat16 g_Am[(size_t)32768 * 512];
__device__ __nv_bfloat16 g_Wh[2 * 512 * 1024];
__device__ __nv_bfloat16 g_Wm[2 * 512 * 1024];

__device__ __forceinline__ uint32_t smem_u32(const void* p) {
    uint32_t a;
    asm("{ .reg .u64 t; cvta.to.shared.u64 t, %1; cvt.u32.u64 %0, t; }" : "=r"(a) : "l"(p));
    return a;
}
__device__ __forceinline__ void cp_async16(uint32_t dst, const void* src) {
    asm volatile("cp.async.cg.shared.global [%0], [%1], 16;" :: "r"(dst), "l"(src));
}
__device__ __forceinline__ void atom_add_release(unsigned int* p, unsigned int v) {
    unsigned int old;
    asm volatile("atom.global.add.release.gpu.u32 %0, [%1], %2;"
                 : "=r"(old) : "l"(p), "r"(v) : "memory");
}
__device__ __forceinline__ unsigned int ld_acquire(const unsigned int* p) {
    unsigned int v;
    asm volatile("ld.global.acquire.gpu.u32 %0, [%1];" : "=r"(v) : "l"(p) : "memory");
    return v;
}

// ---------------- fp32 -> (hi, mid) bf16 split ----------------
__global__ void split2(const float* __restrict__ x,
                       __nv_bfloat16* __restrict__ hi,
                       __nv_bfloat16* __restrict__ mid, int n)
{
    for (int i = blockIdx.x * blockDim.x + threadIdx.x; i < n; i += gridDim.x * blockDim.x) {
        float v = x[i];
        __nv_bfloat16 h = __float2bfloat16(v);
        hi[i] = h;
        mid[i] = __float2bfloat16(v - __bfloat162float(h));
    }
}

// W split (both dirs packed) + hbuf/ctr reset + lengths dtype normalization.
// JAX with x64 disabled silently makes .astype(int64) produce int32; detect width.
__global__ void split2W(const float* __restrict__ Wf, const float* __restrict__ Wb,
                        __nv_bfloat16* __restrict__ hi,
                        __nv_bfloat16* __restrict__ mid, int n,
                        const int* __restrict__ lraw)
{
    int gtid = blockIdx.x * blockDim.x + threadIdx.x;
    if (gtid < 2 * 2 * HID * NB) ((float*)g_hbuf)[gtid] = 0.f;
    if (gtid < 16) ((unsigned int*)g_ctr)[gtid] = 0u;
    if (blockIdx.x == 0) {
        __shared__ int is64;
        if (threadIdx.x == 0) {
            int az = 1;
            for (int i = 1; i < 64; i += 2)
                if (lraw[i] != 0) az = 0;
            is64 = az;
        }
        __syncthreads();
        if (threadIdx.x < NB)
            g_len[threadIdx.x] = is64 ? lraw[2 * threadIdx.x] : lraw[threadIdx.x];
    }
    int total = 2 * n;
    for (int i = gtid; i < total; i += gridDim.x * blockDim.x) {
        float v = (i < n) ? Wf[i] : Wb[i - n];
        __nv_bfloat16 h = __float2bfloat16(v);
        hi[i] = h;
        mid[i] = __float2bfloat16(v - __bfloat162float(h));
    }
}

// ---------------- bf16 HMMA GEMM (2-way split, 3 products: hh, hm, mh) ----------------
#define LDAS 40
#define LDBS 136
#define PLANE_A (128 * LDAS * 2)          // 10240 B
#define PLANE_B (32 * LDBS * 2)           // 8704 B
#define ABUF (2 * PLANE_A)
#define BBUF (2 * PLANE_B)
#define BUFB (ABUF + BBUF)                // 37888 B
#define GEMM_SM_BYTES (2 * BUFB)          // 75776 B (>= epilogue 67584)

__global__ __launch_bounds__(256) void bf16_gemm_bias(
    const __nv_bfloat16* __restrict__ Ah, const __nv_bfloat16* __restrict__ Am,
    const __nv_bfloat16* __restrict__ Wh, const __nv_bfloat16* __restrict__ Wm,
    const float* __restrict__ bf, float* __restrict__ Cf,
    const float* __restrict__ bb, float* __restrict__ Cb,
    int K)
{
    extern __shared__ char sm[];
    const uint32_t smb = smem_u32(sm);
    const int tid = threadIdx.x;
    const int wid = tid >> 5;
    const int warpM = wid & 3;
    const int warpN = wid >> 2;
    const int n0 = blockIdx.x * 128;
    const int m0 = blockIdx.y * 128;
    const size_t zoff = (size_t)blockIdx.z * K * GATES;

    const float* bias = blockIdx.z ? bb : bf;
    float*       C    = blockIdx.z ? Cb : Cf;

    const __nv_bfloat16* APs[2] = {Ah, Am};
    const __nv_bfloat16* WPs[2] = {Wh, Wm};

    wmma::fragment<wmma::accumulator, 16, 16, 16, float> acc[2][4];
#pragma unroll
    for (int i = 0; i < 2; i++)
#pragma unroll
        for (int j = 0; j < 4; j++) wmma::fill_fragment(acc[i][j], 0.0f);

    const int nchunks = K >> 5;

    auto stage = [&](int buf, int c) {
        const int kb = c << 5;
        const uint32_t base = smb + buf * BUFB;
#pragma unroll
        for (int i = 0; i < 4; i++) {
            int idx = tid + (i << 8);
            int plane = idx >> 9, r = idx & 511;
            int row = r >> 2, q = r & 3;
            cp_async16(base + plane * PLANE_A + (row * LDAS + (q << 3)) * 2,
                       APs[plane] + (size_t)(m0 + row) * K + kb + (q << 3));
        }
#pragma unroll
        for (int i = 0; i < 4; i++) {
            int idx = tid + (i << 8);
            int plane = idx >> 9, r = idx & 511;
            int row = r >> 4, q = r & 15;
            cp_async16(base + ABUF + plane * PLANE_B + (row * LDBS + (q << 3)) * 2,
                       WPs[plane] + zoff + (size_t)(kb + row) * GATES + n0 + (q << 3));
        }
        asm volatile("cp.async.commit_group;" ::: "memory");
    };

    stage(0, 0);

    for (int c = 0; c < nchunks; c++) {
        if (c + 1 < nchunks) {
            stage((c + 1) & 1, c + 1);
            asm volatile("cp.async.wait_group 1;" ::: "memory");
        } else {
            asm volatile("cp.async.wait_group 0;" ::: "memory");
        }
        __syncthreads();

        const char* bufp = sm + (c & 1) * BUFB;
#pragma unroll
        for (int ks = 0; ks < 2; ks++) {
            wmma::fragment<wmma::matrix_a, 16, 16, 16, __nv_bfloat16, wmma::row_major> af[2][2];
#pragma unroll
            for (int pa = 0; pa < 2; pa++) {
                const __nv_bfloat16* sA = (const __nv_bfloat16*)(bufp + pa * PLANE_A)
                                          + (warpM * 32) * LDAS + ks * 16;
                wmma::load_matrix_sync(af[pa][0], sA, LDAS);
                wmma::load_matrix_sync(af[pa][1], sA + 16 * LDAS, LDAS);
            }
#pragma unroll
            for (int pb = 0; pb < 2; pb++) {
                const __nv_bfloat16* sB = (const __nv_bfloat16*)(bufp + ABUF + pb * PLANE_B)
                                          + (ks * 16) * LDBS + warpN * 64;
                wmma::fragment<wmma::matrix_b, 16, 16, 16, __nv_bfloat16, wmma::row_major> bfr[4];
#pragma unroll
                for (int j = 0; j < 4; j++)
                    wmma::load_matrix_sync(bfr[j], sB + j * 16, LDBS);
#pragma unroll
                for (int pa = 0; pa < 2; pa++) {
                    if (pa == 1 && pb == 1) continue;   // drop mid*mid (~2^-34)
#pragma unroll
                    for (int i = 0; i < 2; i++)
#pragma unroll
                        for (int j = 0; j < 4; j++)
                            wmma::mma_sync(acc[i][j], af[pa][i], bfr[j], acc[i][j]);
                }
            }
        }
        __syncthreads();
    }

#define LDE 132
    float* sE = (float*)sm;
#pragma unroll
    for (int i = 0; i < 2; i++)
#pragma unroll
        for (int j = 0; j < 4; j++)
            wmma::store_matrix_sync(sE + (warpM * 32 + i * 16) * LDE + warpN * 64 + j * 16,
                                    acc[i][j], LDE, wmma::mem_row_major);
    __syncthreads();

#pragma unroll
    for (int i = 0; i < 16; i++) {
        int idx = tid + (i << 8);
        int row = idx >> 5, q = idx & 31;
        const float4 bv = *(const float4*)(bias + n0 + (q << 2));
        const float* e = sE + row * LDE + (q << 2);
        float4 v = make_float4(e[0] + bv.x, e[1] + bv.y, e[2] + bv.z, e[3] + bv.w);
        *(float4*)(C + (size_t)(m0 + row) * GATES + n0 + (q << 2)) = v;
    }
}

// ---------------- recurrent kernel: HMMA gates (one layer, both directions) ----------------
// grid = 128 CTAs: dir(2) x btile(8, 8 batch each) x ci(8, 32 h-cols each).
// Whh slice resident as bf16 hi/mid smem planes [256][136]; per step the 8x256 h tile
// is gathered from L2 (b-major layout -> 2x LDG.128/thread, fully coalesced), split
// to bf16 planes [16][264] (rows 8-15 zero), and each of 8 warps computes a
// 16(batch)x16(gate-col) wmma tile over 16 k-tiles x 3 products.
// Barrier: release-atomic + acquire-load; outbuf store overlaps the spin window.
#define RW_LD 136          // weight plane ld (bf16 elems)
#define RH_LD 264          // h plane ld (bf16 elems)
#define R_SWH 0                                  // bytes
#define R_SWM (256 * RW_LD * 2)                  // 69632
#define R_SHH (2 * 256 * RW_LD * 2)              // 139264
#define R_SHM (R_SHH + 16 * RH_LD * 2)           // +8448
#define R_SG  (R_SHM + 16 * RH_LD * 2)           // 156160
#define REC_SM_BYTES (R_SG + 16 * 128 * 4)       // 164352

__device__ __forceinline__ float sigm(float x) { return 1.f / (1.f + expf(-x)); }

__global__ __launch_bounds__(256) void lstm_layer(
    const float* __restrict__ wi_f, const float* __restrict__ wi_b,
    const float* __restrict__ Whh_f, const float* __restrict__ Whh_b,
    float* __restrict__ outbuf,        // [TT][NB][OC]
    float* __restrict__ hn, float* __restrict__ cn)   // [2][NB][HID] (this layer)
{
    extern __shared__ char smraw[];
    __nv_bfloat16* sWh = (__nv_bfloat16*)(smraw + R_SWH);
    __nv_bfloat16* sWm = (__nv_bfloat16*)(smraw + R_SWM);
    __nv_bfloat16* sHh = (__nv_bfloat16*)(smraw + R_SHH);
    __nv_bfloat16* sHm = (__nv_bfloat16*)(smraw + R_SHM);
    float*         sG  = (float*)(smraw + R_SG);

    const int dir   = blockIdx.x >> 6;
    const int rem   = blockIdx.x & 63;
    const int btile = rem >> 3;
    const int ci    = rem & 7;
    const int b0    = btile << 3;
    const int tid   = threadIdx.x;
    const int warp  = tid >> 5;

    const float* wi  = dir ? wi_b  : wi_f;
    const float* Whh = dir ? Whh_b : Whh_f;

    // resident weight slice, split to bf16 hi/mid
    for (int idx = tid; idx < 32768; idx += 256) {
        int k = idx >> 7, c = idx & 127;
        int gc = ((c >> 5) << 8) + (ci << 5) + (c & 31);
        float v = __ldg(Whh + (size_t)k * GATES + gc);
        __nv_bfloat16 h = __float2bfloat16(v);
        sWh[k * RW_LD + c] = h;
        sWm[k * RW_LD + c] = __float2bfloat16(v - __bfloat162float(h));
    }
    // zero h planes (incl. pad rows 8-15, read by wmma every step)
    for (int idx = tid; idx < 16 * RH_LD; idx += 256) {
        sHh[idx] = __float2bfloat16(0.f);
        sHm[idx] = __float2bfloat16(0.f);
    }

    // gather mapping: warp = batch row, lanes cover j (coalesced LDG.128)
    const int gb = tid >> 5;          // 0..7 batch within tile
    const int gj = (tid & 31) << 3;   // j0: 8 consecutive h-cols

    // cell ownership: thread owns cell (cj, cb)
    const int cb = tid >> 5;          // 0..7 batch
    const int cj = tid & 31;          // hidden col within our 32
    const int clen = g_len[b0 + cb];
    float cC = 0.f, hC = 0.f;

    unsigned int* ctr = &g_ctr[dir][btile];
    __syncthreads();

    for (int s = 0; s < TT; s++) {
        // gather h tile from L2 (b-major): 2 x LDG.128 per thread, then bf16 split
        {
            const float* hb = g_hbuf[dir][s & 1] + (b0 + gb) * HID + gj;
            float4 v0 = __ldcg((const float4*)hb);
            float4 v1 = __ldcg((const float4*)hb + 1);
            float vv[8] = {v0.x, v0.y, v0.z, v0.w, v1.x, v1.y, v1.z, v1.w};
            __nv_bfloat16 hh[8], mm[8];
#pragma unroll
            for (int q = 0; q < 8; q++) {
                __nv_bfloat16 h = __float2bfloat16(vv[q]);
                hh[q] = h;
                mm[q] = __float2bfloat16(vv[q] - __bfloat162float(h));
            }
            *(uint4*)(sHh + gb * RH_LD + gj) = *(uint4*)hh;
            *(uint4*)(sHm + gb * RH_LD + gj) = *(uint4*)mm;
        }
        const int t = dir ? (TT - 1 - s) : s;

        // wi loads for own cell's 4 gates; consumed after mma (latency hidden)
        const float* wrow = wi + ((size_t)t * NB + b0 + cb) * GATES + (ci << 5) + cj;
        float w0 = __ldg(wrow + 0);
        float w1 = __ldg(wrow + 256);
        float w2 = __ldg(wrow + 512);
        float w3 = __ldg(wrow + 768);
        __syncthreads();

        // gates = h @ Whh via HMMA: warp handles cols [warp*16, warp*16+16)
        {
            wmma::fragment<wmma::accumulator, 16, 16, 16, float> acc;
            wmma::fill_fragment(acc, 0.0f);
#pragma unroll
            for (int kt = 0; kt < 16; kt++) {
                wmma::fragment<wmma::matrix_a, 16, 16, 16, __nv_bfloat16, wmma::row_major> ah, am;
                wmma::fragment<wmma::matrix_b, 16, 16, 16, __nv_bfloat16, wmma::row_major> bh, bm;
                wmma::load_matrix_sync(ah, sHh + kt * 16, RH_LD);
                wmma::load_matrix_sync(am, sHm + kt * 16, RH_LD);
                wmma::load_matrix_sync(bh, sWh + (kt * 16) * RW_LD + warp * 16, RW_LD);
                wmma::load_matrix_sync(bm, sWm + (kt * 16) * RW_LD + warp * 16, RW_LD);
                wmma::mma_sync(acc, ah, bh, acc);
                wmma::mma_sync(acc, ah, bm, acc);
                wmma::mma_sync(acc, am, bh, acc);
            }
            wmma::store_matrix_sync(sG + warp * 16, acc, 128, wmma::mem_row_major);
        }
        __syncthreads();

        float ov;
        {   // cell update: one cell per thread; sG[b][gate*32 + cj]
            const float* gr = sG + cb * 128 + cj;
            float gi = gr[0] + w0, gf = gr[32] + w1, go = gr[64] + w2, gc = gr[96] + w3;
            float cN = sigm(gf + 1.f) * cC + sigm(gi) * tanhf(gc);
            float hN = sigm(go) * tanhf(cN);
            ov = 0.f;
            if (t < clen) { cC = cN; hC = hN; ov = hN; }
            // b-major h store: lanes (cj) consecutive -> 128B burst per warp
            __stcg(&g_hbuf[dir][(s + 1) & 1][(b0 + cb) * HID + (ci << 5) + cj], hC);
        }

        // release h stores, then overlap the DRAM outbuf store with the spin
        __syncthreads();
        if (tid == 0) atom_add_release(ctr, 1u);
        outbuf[((size_t)s * NB + b0 + cb) * OC + (dir << 8) + (ci << 5) + cj] = ov;
        if (tid == 0) {
            unsigned int target = (unsigned int)((s + 1) << 3);
            while (ld_acquire(ctr) < target) __nanosleep(32);
        }
        __syncthreads();
    }

    hn[((size_t)dir * NB + b0 + cb) * HID + (ci << 5) + cj] = hC;
    cn[((size_t)dir * NB + b0 + cb) * HID + (ci << 5) + cj] = cC;
}

// ---------------- launcher ----------------
extern "C" void kernel_launch(void* const* d_in, const int* in_sizes, int n_in,
                              void* d_out, int out_size)
{
    const float* inputs  = (const float*)d_in[0];
    const int*   lengths = (const int*)d_in[1];   // width auto-detected on device
    const float* Wih_f0 = (const float*)d_in[2];
    const float* Whh_f0 = (const float*)d_in[3];
    const float* b_f0   = (const float*)d_in[4];
    const float* Wih_b0 = (const float*)d_in[5];
    const float* Whh_b0 = (const float*)d_in[6];
    const float* b_b0   = (const float*)d_in[7];
    const float* Wih_f1 = (const float*)d_in[8];
    const float* Whh_f1 = (const float*)d_in[9];
    const float* b_f1   = (const float*)d_in[10];
    const float* Wih_b1 = (const float*)d_in[11];
    const float* Whh_b1 = (const float*)d_in[12];
    const float* b_b1   = (const float*)d_in[13];
    float* out = (float*)d_out;

    float *wi_f, *wi_b, *x1;
    __nv_bfloat16 *Ah, *Am, *Wh, *Wm;
    cudaGetSymbolAddress((void**)&wi_f, g_wi_f);
    cudaGetSymbolAddress((void**)&wi_b, g_wi_b);
    cudaGetSymbolAddress((void**)&x1,  g_x1);
    cudaGetSymbolAddress((void**)&Ah, g_Ah);
    cudaGetSymbolAddress((void**)&Am, g_Am);
    cudaGetSymbolAddress((void**)&Wh, g_Wh);
    cudaGetSymbolAddress((void**)&Wm, g_Wm);

    cudaFuncSetAttribute(lstm_layer, cudaFuncAttributeMaxDynamicSharedMemorySize, REC_SM_BYTES);
    cudaFuncSetAttribute(bf16_gemm_bias, cudaFuncAttributeMaxDynamicSharedMemorySize, GEMM_SM_BYTES);

    float* hn0 = out + (size_t)TT * NB * OC;          // hn: (4, B, H)
    float* cn0 = hn0 + 4 * NB * HID;                  // cn: (4, B, H)

    dim3 gGrid(8, 256, 2);   // N tiles x M tiles x direction

    // ---- layer 0 (slot #4 = lstm_layer for ncu) ----
    split2<<<1024, 256>>>(inputs, Ah, Am, TT * NB * IN0);                   // 1
    split2W<<<256, 256>>>(Wih_f0, Wih_b0, Wh, Wm, IN0 * GATES, lengths);    // 2 (+reset)
    bf16_gemm_bias<<<gGrid, 256, GEMM_SM_BYTES>>>(Ah, Am, Wh, Wm,           // 3
                                                  b_f0, wi_f, b_b0, wi_b, IN0);
    lstm_layer<<<128, 256, REC_SM_BYTES>>>(wi_f, wi_b, Whh_f0, Whh_b0, x1,  // 4
                                           hn0, cn0);

    // ---- layer 1 ----
    split2<<<1024, 256>>>(x1, Ah, Am, TT * NB * OC);
    split2W<<<512, 256>>>(Wih_f1, Wih_b1, Wh, Wm, OC * GATES, lengths);     // re-resets hbuf/ctr
    bf16_gemm_bias<<<gGrid, 256, GEMM_SM_BYTES>>>(Ah, Am, Wh, Wm,
                                                  b_f1, wi_f, b_b1, wi_b, OC);
    lstm_layer<<<128, 256, REC_SM_BYTES>>>(wi_f, wi_b, Whh_f1, Whh_b1, out,
                                           hn0 + 2 * NB * HID, cn0 + 2 * NB * HID);
}

// round 15
// speedup vs baseline: 1.8093x; 1.2453x over previous
#include <cuda_runtime.h>
#include <cuda_bf16.h>
#include <mma.h>
#include <cstdint>

using namespace nvcuda;

#define TT   512
#define NB   64
#define IN0  256
#define HID  256
#define GATES 1024
#define OC   512   // 2*HID

// ---------------- scratch (static device memory; no allocation) ----------------
__device__ float g_wi_f[(size_t)TT * NB * GATES];  // 128 MB
__device__ float g_wi_b[(size_t)TT * NB * GATES];  // 128 MB
__device__ float g_x1 [(size_t)TT * NB * OC];      // 64 MB (layer-0 out / layer-1 in)
__device__ float g_hbuf[2][2][NB * HID];           // [dir][slot][b*256 + j]  (b-major)
__device__ unsigned int g_ctr[2][8];               // [dir][bgroup] step barrier counters
__device__ int g_len[NB];                          // normalized lengths (int32)

// bf16 2-way split planes (A shared across layers; W holds both dirs back-to-back)
__device__ __nv_bfloat16 g_Ah[(size_t)32768 * 512];
__device__ __nv_bfloat16 g_Am[(size_t)32768 * 512];
__device__ __nv_bfloat16 g_Wh[2 * 512 * 1024];
__device__ __nv_bfloat16 g_Wm[2 * 512 * 1024];

__device__ __forceinline__ uint32_t smem_u32(const void* p) {
    uint32_t a;
    asm("{ .reg .u64 t; cvta.to.shared.u64 t, %1; cvt.u32.u64 %0, t; }" : "=r"(a) : "l"(p));
    return a;
}
__device__ __forceinline__ void cp_async16(uint32_t dst, const void* src) {
    asm volatile("cp.async.cg.shared.global [%0], [%1], 16;" :: "r"(dst), "l"(src));
}
__device__ __forceinline__ void atom_add_release(unsigned int* p, unsigned int v) {
    unsigned int old;
    asm volatile("atom.global.add.release.gpu.u32 %0, [%1], %2;"
                 : "=r"(old) : "l"(p), "r"(v) : "memory");
}
__device__ __forceinline__ unsigned int ld_acquire(const unsigned int* p) {
    unsigned int v;
    asm volatile("ld.global.acquire.gpu.u32 %0, [%1];" : "=r"(v) : "l"(p) : "memory");
    return v;
}

// ---------------- fp32 -> (hi, mid) bf16 split ----------------
__global__ void split2(const float* __restrict__ x,
                       __nv_bfloat16* __restrict__ hi,
                       __nv_bfloat16* __restrict__ mid, int n)
{
    for (int i = blockIdx.x * blockDim.x + threadIdx.x; i < n; i += gridDim.x * blockDim.x) {
        float v = x[i];
        __nv_bfloat16 h = __float2bfloat16(v);
        hi[i] = h;
        mid[i] = __float2bfloat16(v - __bfloat162float(h));
    }
}

// W split (both dirs packed) + hbuf/ctr reset + lengths dtype normalization.
// JAX with x64 disabled silently makes .astype(int64) produce int32; detect width.
__global__ void split2W(const float* __restrict__ Wf, const float* __restrict__ Wb,
                        __nv_bfloat16* __restrict__ hi,
                        __nv_bfloat16* __restrict__ mid, int n,
                        const int* __restrict__ lraw)
{
    int gtid = blockIdx.x * blockDim.x + threadIdx.x;
    if (gtid < 2 * 2 * HID * NB) ((float*)g_hbuf)[gtid] = 0.f;
    if (gtid < 16) ((unsigned int*)g_ctr)[gtid] = 0u;
    if (blockIdx.x == 0) {
        __shared__ int is64;
        if (threadIdx.x == 0) {
            int az = 1;
            for (int i = 1; i < 64; i += 2)
                if (lraw[i] != 0) az = 0;
            is64 = az;
        }
        __syncthreads();
        if (threadIdx.x < NB)
            g_len[threadIdx.x] = is64 ? lraw[2 * threadIdx.x] : lraw[threadIdx.x];
    }
    int total = 2 * n;
    for (int i = gtid; i < total; i += gridDim.x * blockDim.x) {
        float v = (i < n) ? Wf[i] : Wb[i - n];
        __nv_bfloat16 h = __float2bfloat16(v);
        hi[i] = h;
        mid[i] = __float2bfloat16(v - __bfloat162float(h));
    }
}

// ---------------- bf16 HMMA GEMM (2-way split, 3 products: hh, hm, mh) ----------------
#define LDAS 40
#define LDBS 136
#define PLANE_A (128 * LDAS * 2)          // 10240 B
#define PLANE_B (32 * LDBS * 2)           // 8704 B
#define ABUF (2 * PLANE_A)
#define BBUF (2 * PLANE_B)
#define BUFB (ABUF + BBUF)                // 37888 B
#define GEMM_SM_BYTES (2 * BUFB)          // 75776 B (>= epilogue 67584)

__global__ __launch_bounds__(256) void bf16_gemm_bias(
    const __nv_bfloat16* __restrict__ Ah, const __nv_bfloat16* __restrict__ Am,
    const __nv_bfloat16* __restrict__ Wh, const __nv_bfloat16* __restrict__ Wm,
    const float* __restrict__ bf, float* __restrict__ Cf,
    const float* __restrict__ bb, float* __restrict__ Cb,
    int K)
{
    extern __shared__ char sm[];
    const uint32_t smb = smem_u32(sm);
    const int tid = threadIdx.x;
    const int wid = tid >> 5;
    const int warpM = wid & 3;
    const int warpN = wid >> 2;
    const int n0 = blockIdx.x * 128;
    const int m0 = blockIdx.y * 128;
    const size_t zoff = (size_t)blockIdx.z * K * GATES;

    const float* bias = blockIdx.z ? bb : bf;
    float*       C    = blockIdx.z ? Cb : Cf;

    const __nv_bfloat16* APs[2] = {Ah, Am};
    const __nv_bfloat16* WPs[2] = {Wh, Wm};

    wmma::fragment<wmma::accumulator, 16, 16, 16, float> acc[2][4];
#pragma unroll
    for (int i = 0; i < 2; i++)
#pragma unroll
        for (int j = 0; j < 4; j++) wmma::fill_fragment(acc[i][j], 0.0f);

    const int nchunks = K >> 5;

    auto stage = [&](int buf, int c) {
        const int kb = c << 5;
        const uint32_t base = smb + buf * BUFB;
#pragma unroll
        for (int i = 0; i < 4; i++) {
            int idx = tid + (i << 8);
            int plane = idx >> 9, r = idx & 511;
            int row = r >> 2, q = r & 3;
            cp_async16(base + plane * PLANE_A + (row * LDAS + (q << 3)) * 2,
                       APs[plane] + (size_t)(m0 + row) * K + kb + (q << 3));
        }
#pragma unroll
        for (int i = 0; i < 4; i++) {
            int idx = tid + (i << 8);
            int plane = idx >> 9, r = idx & 511;
            int row = r >> 4, q = r & 15;
            cp_async16(base + ABUF + plane * PLANE_B + (row * LDBS + (q << 3)) * 2,
                       WPs[plane] + zoff + (size_t)(kb + row) * GATES + n0 + (q << 3));
        }
        asm volatile("cp.async.commit_group;" ::: "memory");
    };

    stage(0, 0);

    for (int c = 0; c < nchunks; c++) {
        if (c + 1 < nchunks) {
            stage((c + 1) & 1, c + 1);
            asm volatile("cp.async.wait_group 1;" ::: "memory");
        } else {
            asm volatile("cp.async.wait_group 0;" ::: "memory");
        }
        __syncthreads();

        const char* bufp = sm + (c & 1) * BUFB;
#pragma unroll
        for (int ks = 0; ks < 2; ks++) {
            wmma::fragment<wmma::matrix_a, 16, 16, 16, __nv_bfloat16, wmma::row_major> af[2][2];
#pragma unroll
            for (int pa = 0; pa < 2; pa++) {
                const __nv_bfloat16* sA = (const __nv_bfloat16*)(bufp + pa * PLANE_A)
                                          + (warpM * 32) * LDAS + ks * 16;
                wmma::load_matrix_sync(af[pa][0], sA, LDAS);
                wmma::load_matrix_sync(af[pa][1], sA + 16 * LDAS, LDAS);
            }
#pragma unroll
            for (int pb = 0; pb < 2; pb++) {
                const __nv_bfloat16* sB = (const __nv_bfloat16*)(bufp + ABUF + pb * PLANE_B)
                                          + (ks * 16) * LDBS + warpN * 64;
                wmma::fragment<wmma::matrix_b, 16, 16, 16, __nv_bfloat16, wmma::row_major> bfr[4];
#pragma unroll
                for (int j = 0; j < 4; j++)
                    wmma::load_matrix_sync(bfr[j], sB + j * 16, LDBS);
#pragma unroll
                for (int pa = 0; pa < 2; pa++) {
                    if (pa == 1 && pb == 1) continue;   // drop mid*mid (~2^-34)
#pragma unroll
                    for (int i = 0; i < 2; i++)
#pragma unroll
                        for (int j = 0; j < 4; j++)
                            wmma::mma_sync(acc[i][j], af[pa][i], bfr[j], acc[i][j]);
                }
            }
        }
        __syncthreads();
    }

#define LDE 132
    float* sE = (float*)sm;
#pragma unroll
    for (int i = 0; i < 2; i++)
#pragma unroll
        for (int j = 0; j < 4; j++)
            wmma::store_matrix_sync(sE + (warpM * 32 + i * 16) * LDE + warpN * 64 + j * 16,
                                    acc[i][j], LDE, wmma::mem_row_major);
    __syncthreads();

#pragma unroll
    for (int i = 0; i < 16; i++) {
        int idx = tid + (i << 8);
        int row = idx >> 5, q = idx & 31;
        const float4 bv = *(const float4*)(bias + n0 + (q << 2));
        const float* e = sE + row * LDE + (q << 2);
        float4 v = make_float4(e[0] + bv.x, e[1] + bv.y, e[2] + bv.z, e[3] + bv.w);
        *(float4*)(C + (size_t)(m0 + row) * GATES + n0 + (q << 2)) = v;
    }
}

// ---------------- recurrent kernel: HMMA gates, 16-batch packed ----------------
// grid = 128 CTAs: dir(2) x bgroup(4, 16 batches) x ci(16, 16 cells / 64 gate-cols).
// Whh slice resident as bf16 hi/mid planes [256][72]; per step the 16x256 h tile is
// gathered coalesced from b-major L2 buffer, split to bf16 planes [16][264], and
// 8 warps = 4 n-tiles x 2 k-halves compute 16x16 wmma tiles (8 kt x 3 products,
// dual accumulators). No zero-row padding. Barrier: 16-CTA release/acquire counter.
#define RW_LD 72           // weight plane ld (bf16 elems)
#define RH_LD 264          // h plane ld (bf16 elems)
#define SG_LD 72
#define R_SWH 0
#define R_SWM (256 * RW_LD * 2)                  // 36864
#define R_SHH (2 * 256 * RW_LD * 2)              // 73728
#define R_SHM (R_SHH + 16 * RH_LD * 2)           // 82176
#define R_SG  (R_SHM + 16 * RH_LD * 2)           // 90624
#define REC_SM_BYTES (R_SG + 2 * 16 * SG_LD * 4) // 99840

__device__ __forceinline__ float sigm(float x) { return 1.f / (1.f + expf(-x)); }

__global__ __launch_bounds__(256, 1) void lstm_layer(
    const float* __restrict__ wi_f, const float* __restrict__ wi_b,
    const float* __restrict__ Whh_f, const float* __restrict__ Whh_b,
    float* __restrict__ outbuf,        // [TT][NB][OC]
    float* __restrict__ hn, float* __restrict__ cn)   // [2][NB][HID] (this layer)
{
    extern __shared__ char smraw[];
    __nv_bfloat16* sWh = (__nv_bfloat16*)(smraw + R_SWH);
    __nv_bfloat16* sWm = (__nv_bfloat16*)(smraw + R_SWM);
    __nv_bfloat16* sHh = (__nv_bfloat16*)(smraw + R_SHH);
    __nv_bfloat16* sHm = (__nv_bfloat16*)(smraw + R_SHM);
    float*         sG  = (float*)(smraw + R_SG);

    const int dir    = blockIdx.x >> 6;
    const int rem    = blockIdx.x & 63;
    const int bgroup = rem >> 4;        // 0..3, 16 batches
    const int ci     = rem & 15;        // 0..15, cells [ci*16, ci*16+16)
    const int b0     = bgroup << 4;
    const int tid    = threadIdx.x;
    const int warp   = tid >> 5;
    const int ntile  = warp & 3;        // 16-col tile within our 64 gate-cols
    const int khalf  = warp >> 2;       // k-range half

    const float* wi  = dir ? wi_b  : wi_f;
    const float* Whh = dir ? Whh_b : Whh_f;

    // resident weight slice [256 k][64 cc], split to bf16 hi/mid
    // cc = g*16 + j16  ->  gate col gc = g*256 + ci*16 + j16
    for (int idx = tid; idx < 16384; idx += 256) {
        int k = idx >> 6, cc = idx & 63;
        int gc = ((cc >> 4) << 8) + (ci << 4) + (cc & 15);
        float v = __ldg(Whh + (size_t)k * GATES + gc);
        __nv_bfloat16 h = __float2bfloat16(v);
        sWh[k * RW_LD + cc] = h;
        sWm[k * RW_LD + cc] = __float2bfloat16(v - __bfloat162float(h));
    }

    // gather mapping: 16 threads per batch row, each 16 consecutive j
    const int gb = tid >> 4;            // 0..15 batch within group
    const int gj = (tid & 15) << 4;     // j0

    // cell ownership: thread owns cell (cj, cb)
    const int cb = tid >> 4;            // 0..15 batch
    const int cj = tid & 15;            // cell col within our 16
    const int clen = g_len[b0 + cb];
    float cC = 0.f, hC = 0.f;

    unsigned int* ctr = &g_ctr[dir][bgroup];
    __syncthreads();

    for (int s = 0; s < TT; s++) {
        // gather h tile (coalesced: 4x LDG.128 per thread), split to bf16 planes
        {
            const float* hb = g_hbuf[dir][s & 1] + (b0 + gb) * HID + gj;
            float4 v0 = __ldcg((const float4*)hb);
            float4 v1 = __ldcg((const float4*)hb + 1);
            float4 v2 = __ldcg((const float4*)hb + 2);
            float4 v3 = __ldcg((const float4*)hb + 3);
            float vv[16] = {v0.x, v0.y, v0.z, v0.w, v1.x, v1.y, v1.z, v1.w,
                            v2.x, v2.y, v2.z, v2.w, v3.x, v3.y, v3.z, v3.w};
            __nv_bfloat16 hh[16], mm[16];
#pragma unroll
            for (int q = 0; q < 16; q++) {
                __nv_bfloat16 h = __float2bfloat16(vv[q]);
                hh[q] = h;
                mm[q] = __float2bfloat16(vv[q] - __bfloat162float(h));
            }
            *(uint4*)(sHh + gb * RH_LD + gj)     = *(uint4*)hh;
            *(uint4*)(sHh + gb * RH_LD + gj + 8) = *(uint4*)(hh + 8);
            *(uint4*)(sHm + gb * RH_LD + gj)     = *(uint4*)mm;
            *(uint4*)(sHm + gb * RH_LD + gj + 8) = *(uint4*)(mm + 8);
        }
        const int t = dir ? (TT - 1 - s) : s;

        // wi loads for own cell's 4 gates; consumed after mma (latency hidden)
        const float* wrow = wi + ((size_t)t * NB + b0 + cb) * GATES + (ci << 4) + cj;
        float w0 = __ldg(wrow + 0);
        float w1 = __ldg(wrow + 256);
        float w2 = __ldg(wrow + 512);
        float w3 = __ldg(wrow + 768);
        __syncthreads();

        // gates = h @ Whh via HMMA: warp -> n-tile ntile, k-half khalf.
        // dual accumulators (even/odd kt) halve the dependent HMMA chain.
        {
            wmma::fragment<wmma::accumulator, 16, 16, 16, float> acc0, acc1;
            wmma::fill_fragment(acc0, 0.0f);
            wmma::fill_fragment(acc1, 0.0f);
#pragma unroll
            for (int q = 0; q < 4; q++) {
#pragma unroll
                for (int e = 0; e < 2; e++) {
                    int kt = (khalf << 3) + (q << 1) + e;
                    wmma::fragment<wmma::matrix_a, 16, 16, 16, __nv_bfloat16, wmma::row_major> ah, am;
                    wmma::fragment<wmma::matrix_b, 16, 16, 16, __nv_bfloat16, wmma::row_major> bh, bm;
                    wmma::load_matrix_sync(ah, sHh + kt * 16, RH_LD);
                    wmma::load_matrix_sync(am, sHm + kt * 16, RH_LD);
                    wmma::load_matrix_sync(bh, sWh + (kt * 16) * RW_LD + ntile * 16, RW_LD);
                    wmma::load_matrix_sync(bm, sWm + (kt * 16) * RW_LD + ntile * 16, RW_LD);
                    if (e == 0) {
                        wmma::mma_sync(acc0, ah, bh, acc0);
                        wmma::mma_sync(acc0, ah, bm, acc0);
                        wmma::mma_sync(acc0, am, bh, acc0);
                    } else {
                        wmma::mma_sync(acc1, ah, bh, acc1);
                        wmma::mma_sync(acc1, ah, bm, acc1);
                        wmma::mma_sync(acc1, am, bh, acc1);
                    }
                }
            }
#pragma unroll
            for (int e = 0; e < acc0.num_elements; e++) acc0.x[e] += acc1.x[e];
            wmma::store_matrix_sync(sG + khalf * (16 * SG_LD) + ntile * 16,
                                    acc0, SG_LD, wmma::mem_row_major);
        }
        __syncthreads();

        float ov;
        {   // cell update: sum k-half partials; sG[khalf][b][g*16 + cj]
            const float* g0 = sG + cb * SG_LD;
            const float* g1 = g0 + 16 * SG_LD;
            float gi = g0[cj]      + g1[cj]      + w0;
            float gf = g0[16 + cj] + g1[16 + cj] + w1;
            float go = g0[32 + cj] + g1[32 + cj] + w2;
            float gc = g0[48 + cj] + g1[48 + cj] + w3;
            float cN = sigm(gf + 1.f) * cC + sigm(gi) * tanhf(gc);
            float hN = sigm(go) * tanhf(cN);
            ov = 0.f;
            if (t < clen) { cC = cN; hC = hN; ov = hN; }
            // b-major h store: half-warp lanes consecutive -> coalesced bursts
            __stcg(&g_hbuf[dir][(s + 1) & 1][(b0 + cb) * HID + (ci << 4) + cj], hC);
        }

        // release h stores, then overlap DRAM outbuf store with the spin window
        __syncthreads();
        if (tid == 0) atom_add_release(ctr, 1u);
        outbuf[((size_t)s * NB + b0 + cb) * OC + (dir << 8) + (ci << 4) + cj] = ov;
        if (tid == 0) {
            unsigned int target = (unsigned int)((s + 1) << 4);
            while (ld_acquire(ctr) < target) __nanosleep(32);
        }
        __syncthreads();
    }

    hn[((size_t)dir * NB + b0 + cb) * HID + (ci << 4) + cj] = hC;
    cn[((size_t)dir * NB + b0 + cb) * HID + (ci << 4) + cj] = cC;
}

// ---------------- launcher ----------------
extern "C" void kernel_launch(void* const* d_in, const int* in_sizes, int n_in,
                              void* d_out, int out_size)
{
    const float* inputs  = (const float*)d_in[0];
    const int*   lengths = (const int*)d_in[1];   // width auto-detected on device
    const float* Wih_f0 = (const float*)d_in[2];
    const float* Whh_f0 = (const float*)d_in[3];
    const float* b_f0   = (const float*)d_in[4];
    const float* Wih_b0 = (const float*)d_in[5];
    const float* Whh_b0 = (const float*)d_in[6];
    const float* b_b0   = (const float*)d_in[7];
    const float* Wih_f1 = (const float*)d_in[8];
    const float* Whh_f1 = (const float*)d_in[9];
    const float* b_f1   = (const float*)d_in[10];
    const float* Wih_b1 = (const float*)d_in[11];
    const float* Whh_b1 = (const float*)d_in[12];
    const float* b_b1   = (const float*)d_in[13];
    float* out = (float*)d_out;

    float *wi_f, *wi_b, *x1;
    __nv_bfloat16 *Ah, *Am, *Wh, *Wm;
    cudaGetSymbolAddress((void**)&wi_f, g_wi_f);
    cudaGetSymbolAddress((void**)&wi_b, g_wi_b);
    cudaGetSymbolAddress((void**)&x1,  g_x1);
    cudaGetSymbolAddress((void**)&Ah, g_Ah);
    cudaGetSymbolAddress((void**)&Am, g_Am);
    cudaGetSymbolAddress((void**)&Wh, g_Wh);
    cudaGetSymbolAddress((void**)&Wm, g_Wm);

    cudaFuncSetAttribute(lstm_layer, cudaFuncAttributeMaxDynamicSharedMemorySize, REC_SM_BYTES);
    cudaFuncSetAttribute(bf16_gemm_bias, cudaFuncAttributeMaxDynamicSharedMemorySize, GEMM_SM_BYTES);

    float* hn0 = out + (size_t)TT * NB * OC;          // hn: (4, B, H)
    float* cn0 = hn0 + 4 * NB * HID;                  // cn: (4, B, H)

    dim3 gGrid(8, 256, 2);   // N tiles x M tiles x direction

    // ---- layer 0 (slot #4 = lstm_layer for ncu) ----
    split2<<<1024, 256>>>(inputs, Ah, Am, TT * NB * IN0);                   // 1
    split2W<<<256, 256>>>(Wih_f0, Wih_b0, Wh, Wm, IN0 * GATES, lengths);    // 2 (+reset)
    bf16_gemm_bias<<<gGrid, 256, GEMM_SM_BYTES>>>(Ah, Am, Wh, Wm,           // 3
                                                  b_f0, wi_f, b_b0, wi_b, IN0);
    lstm_layer<<<128, 256, REC_SM_BYTES>>>(wi_f, wi_b, Whh_f0, Whh_b0, x1,  // 4
                                           hn0, cn0);

    // ---- layer 1 ----
    split2<<<1024, 256>>>(x1, Ah, Am, TT * NB * OC);
    split2W<<<512, 256>>>(Wih_f1, Wih_b1, Wh, Wm, OC * GATES, lengths);     // re-resets hbuf/ctr
    bf16_gemm_bias<<<gGrid, 256, GEMM_SM_BYTES>>>(Ah, Am, Wh, Wm,
                                                  b_f1, wi_f, b_b1, wi_b, OC);
    lstm_layer<<<128, 256, REC_SM_BYTES>>>(wi_f, wi_b, Whh_f1, Whh_b1, out,
                                           hn0 + 2 * NB * HID, cn0 + 2 * NB * HID);
}

// round 16
// speedup vs baseline: 1.8898x; 1.0445x over previous
#include <cuda_runtime.h>
#include <cuda_bf16.h>
#include <mma.h>
#include <cstdint>

using namespace nvcuda;

#define TT   512
#define NB   64
#define IN0  256
#define HID  256
#define GATES 1024
#define OC   512   // 2*HID

// ---------------- scratch (static device memory; no allocation) ----------------
__device__ float g_wi_f[(size_t)TT * NB * GATES];  // 128 MB
__device__ float g_wi_b[(size_t)TT * NB * GATES];  // 128 MB
__device__ float g_x1 [(size_t)TT * NB * OC];      // 64 MB (layer-0 out / layer-1 in)
__device__ float g_hbuf[2][2][NB * HID];           // [dir][slot][b*256 + j]  (b-major)
__device__ unsigned int g_ctr[2][8];               // [dir][bgroup] step barrier counters
__device__ int g_len[NB];                          // normalized lengths (int32)

// bf16 2-way split planes (A shared across layers; W holds both dirs back-to-back)
__device__ __nv_bfloat16 g_Ah[(size_t)32768 * 512];
__device__ __nv_bfloat16 g_Am[(size_t)32768 * 512];
__device__ __nv_bfloat16 g_Wh[2 * 512 * 1024];
__device__ __nv_bfloat16 g_Wm[2 * 512 * 1024];

__device__ __forceinline__ uint32_t smem_u32(const void* p) {
    uint32_t a;
    asm("{ .reg .u64 t; cvta.to.shared.u64 t, %1; cvt.u32.u64 %0, t; }" : "=r"(a) : "l"(p));
    return a;
}
__device__ __forceinline__ void cp_async16(uint32_t dst, const void* src) {
    asm volatile("cp.async.cg.shared.global [%0], [%1], 16;" :: "r"(dst), "l"(src));
}
__device__ __forceinline__ void atom_add_release(unsigned int* p, unsigned int v) {
    unsigned int old;
    asm volatile("atom.global.add.release.gpu.u32 %0, [%1], %2;"
                 : "=r"(old) : "l"(p), "r"(v) : "memory");
}
__device__ __forceinline__ unsigned int ld_acquire(const unsigned int* p) {
    unsigned int v;
    asm volatile("ld.global.acquire.gpu.u32 %0, [%1];" : "=r"(v) : "l"(p) : "memory");
    return v;
}

// ---------------- fp32 -> (hi, mid) bf16 split ----------------
__global__ void split2(const float* __restrict__ x,
                       __nv_bfloat16* __restrict__ hi,
                       __nv_bfloat16* __restrict__ mid, int n)
{
    for (int i = blockIdx.x * blockDim.x + threadIdx.x; i < n; i += gridDim.x * blockDim.x) {
        float v = x[i];
        __nv_bfloat16 h = __float2bfloat16(v);
        hi[i] = h;
        mid[i] = __float2bfloat16(v - __bfloat162float(h));
    }
}

// W split (both dirs packed) + hbuf/ctr reset + lengths dtype normalization.
// JAX with x64 disabled silently makes .astype(int64) produce int32; detect width.
__global__ void split2W(const float* __restrict__ Wf, const float* __restrict__ Wb,
                        __nv_bfloat16* __restrict__ hi,
                        __nv_bfloat16* __restrict__ mid, int n,
                        const int* __restrict__ lraw)
{
    int gtid = blockIdx.x * blockDim.x + threadIdx.x;
    if (gtid < 2 * 2 * HID * NB) ((float*)g_hbuf)[gtid] = 0.f;
    if (gtid < 16) ((unsigned int*)g_ctr)[gtid] = 0u;
    if (blockIdx.x == 0) {
        __shared__ int is64;
        if (threadIdx.x == 0) {
            int az = 1;
            for (int i = 1; i < 64; i += 2)
                if (lraw[i] != 0) az = 0;
            is64 = az;
        }
        __syncthreads();
        if (threadIdx.x < NB)
            g_len[threadIdx.x] = is64 ? lraw[2 * threadIdx.x] : lraw[threadIdx.x];
    }
    int total = 2 * n;
    for (int i = gtid; i < total; i += gridDim.x * blockDim.x) {
        float v = (i < n) ? Wf[i] : Wb[i - n];
        __nv_bfloat16 h = __float2bfloat16(v);
        hi[i] = h;
        mid[i] = __float2bfloat16(v - __bfloat162float(h));
    }
}

// ---------------- bf16 HMMA GEMM (2-way split, 3 products: hh, hm, mh) ----------------
#define LDAS 40
#define LDBS 136
#define PLANE_A (128 * LDAS * 2)          // 10240 B
#define PLANE_B (32 * LDBS * 2)           // 8704 B
#define ABUF (2 * PLANE_A)
#define BBUF (2 * PLANE_B)
#define BUFB (ABUF + BBUF)                // 37888 B
#define GEMM_SM_BYTES (2 * BUFB)          // 75776 B (>= epilogue 67584)

__global__ __launch_bounds__(256) void bf16_gemm_bias(
    const __nv_bfloat16* __restrict__ Ah, const __nv_bfloat16* __restrict__ Am,
    const __nv_bfloat16* __restrict__ Wh, const __nv_bfloat16* __restrict__ Wm,
    const float* __restrict__ bf, float* __restrict__ Cf,
    const float* __restrict__ bb, float* __restrict__ Cb,
    int K)
{
    extern __shared__ char sm[];
    const uint32_t smb = smem_u32(sm);
    const int tid = threadIdx.x;
    const int wid = tid >> 5;
    const int warpM = wid & 3;
    const int warpN = wid >> 2;
    const int n0 = blockIdx.x * 128;
    const int m0 = blockIdx.y * 128;
    const size_t zoff = (size_t)blockIdx.z * K * GATES;

    const float* bias = blockIdx.z ? bb : bf;
    float*       C    = blockIdx.z ? Cb : Cf;

    const __nv_bfloat16* APs[2] = {Ah, Am};
    const __nv_bfloat16* WPs[2] = {Wh, Wm};

    wmma::fragment<wmma::accumulator, 16, 16, 16, float> acc[2][4];
#pragma unroll
    for (int i = 0; i < 2; i++)
#pragma unroll
        for (int j = 0; j < 4; j++) wmma::fill_fragment(acc[i][j], 0.0f);

    const int nchunks = K >> 5;

    auto stage = [&](int buf, int c) {
        const int kb = c << 5;
        const uint32_t base = smb + buf * BUFB;
#pragma unroll
        for (int i = 0; i < 4; i++) {
            int idx = tid + (i << 8);
            int plane = idx >> 9, r = idx & 511;
            int row = r >> 2, q = r & 3;
            cp_async16(base + plane * PLANE_A + (row * LDAS + (q << 3)) * 2,
                       APs[plane] + (size_t)(m0 + row) * K + kb + (q << 3));
        }
#pragma unroll
        for (int i = 0; i < 4; i++) {
            int idx = tid + (i << 8);
            int plane = idx >> 9, r = idx & 511;
            int row = r >> 4, q = r & 15;
            cp_async16(base + ABUF + plane * PLANE_B + (row * LDBS + (q << 3)) * 2,
                       WPs[plane] + zoff + (size_t)(kb + row) * GATES + n0 + (q << 3));
        }
        asm volatile("cp.async.commit_group;" ::: "memory");
    };

    stage(0, 0);

    for (int c = 0; c < nchunks; c++) {
        if (c + 1 < nchunks) {
            stage((c + 1) & 1, c + 1);
            asm volatile("cp.async.wait_group 1;" ::: "memory");
        } else {
            asm volatile("cp.async.wait_group 0;" ::: "memory");
        }
        __syncthreads();

        const char* bufp = sm + (c & 1) * BUFB;
#pragma unroll
        for (int ks = 0; ks < 2; ks++) {
            wmma::fragment<wmma::matrix_a, 16, 16, 16, __nv_bfloat16, wmma::row_major> af[2][2];
#pragma unroll
            for (int pa = 0; pa < 2; pa++) {
                const __nv_bfloat16* sA = (const __nv_bfloat16*)(bufp + pa * PLANE_A)
                                          + (warpM * 32) * LDAS + ks * 16;
                wmma::load_matrix_sync(af[pa][0], sA, LDAS);
                wmma::load_matrix_sync(af[pa][1], sA + 16 * LDAS, LDAS);
            }
#pragma unroll
            for (int pb = 0; pb < 2; pb++) {
                const __nv_bfloat16* sB = (const __nv_bfloat16*)(bufp + ABUF + pb * PLANE_B)
                                          + (ks * 16) * LDBS + warpN * 64;
                wmma::fragment<wmma::matrix_b, 16, 16, 16, __nv_bfloat16, wmma::row_major> bfr[4];
#pragma unroll
                for (int j = 0; j < 4; j++)
                    wmma::load_matrix_sync(bfr[j], sB + j * 16, LDBS);
#pragma unroll
                for (int pa = 0; pa < 2; pa++) {
                    if (pa == 1 && pb == 1) continue;   // drop mid*mid (~2^-34)
#pragma unroll
                    for (int i = 0; i < 2; i++)
#pragma unroll
                        for (int j = 0; j < 4; j++)
                            wmma::mma_sync(acc[i][j], af[pa][i], bfr[j], acc[i][j]);
                }
            }
        }
        __syncthreads();
    }

#define LDE 132
    float* sE = (float*)sm;
#pragma unroll
    for (int i = 0; i < 2; i++)
#pragma unroll
        for (int j = 0; j < 4; j++)
            wmma::store_matrix_sync(sE + (warpM * 32 + i * 16) * LDE + warpN * 64 + j * 16,
                                    acc[i][j], LDE, wmma::mem_row_major);
    __syncthreads();

#pragma unroll
    for (int i = 0; i < 16; i++) {
        int idx = tid + (i << 8);
        int row = idx >> 5, q = idx & 31;
        const float4 bv = *(const float4*)(bias + n0 + (q << 2));
        const float* e = sE + row * LDE + (q << 2);
        float4 v = make_float4(e[0] + bv.x, e[1] + bv.y, e[2] + bv.z, e[3] + bv.w);
        *(float4*)(C + (size_t)(m0 + row) * GATES + n0 + (q << 2)) = v;
    }
}

// ---------------- recurrent kernel: HMMA gates, 16-batch packed, 512 threads ----------------
// grid = 128 CTAs: dir(2) x bgroup(4, 16 batches) x ci(16, 16 cells / 64 gate-cols).
// 16 warps = 4 n-tiles x 4 k-quarters: each warp 4 kt x 3 products (dual acc).
// Cell update (threads 0..255) sums the 4 k-partials from sG.
#define RW_LD 72           // weight plane ld (bf16 elems)
#define RH_LD 264          // h plane ld (bf16 elems)
#define SG_LD 72
#define R_SWH 0
#define R_SWM (256 * RW_LD * 2)                  // 36864
#define R_SHH (2 * 256 * RW_LD * 2)              // 73728
#define R_SHM (R_SHH + 16 * RH_LD * 2)           // 82176
#define R_SG  (R_SHM + 16 * RH_LD * 2)           // 90624
#define REC_SM_BYTES (R_SG + 4 * 16 * SG_LD * 4) // 109056

__device__ __forceinline__ float sigm(float x) { return 1.f / (1.f + expf(-x)); }

__global__ __launch_bounds__(512, 1) void lstm_layer(
    const float* __restrict__ wi_f, const float* __restrict__ wi_b,
    const float* __restrict__ Whh_f, const float* __restrict__ Whh_b,
    float* __restrict__ outbuf,        // [TT][NB][OC]
    float* __restrict__ hn, float* __restrict__ cn)   // [2][NB][HID] (this layer)
{
    extern __shared__ char smraw[];
    __nv_bfloat16* sWh = (__nv_bfloat16*)(smraw + R_SWH);
    __nv_bfloat16* sWm = (__nv_bfloat16*)(smraw + R_SWM);
    __nv_bfloat16* sHh = (__nv_bfloat16*)(smraw + R_SHH);
    __nv_bfloat16* sHm = (__nv_bfloat16*)(smraw + R_SHM);
    float*         sG  = (float*)(smraw + R_SG);

    const int dir    = blockIdx.x >> 6;
    const int rem    = blockIdx.x & 63;
    const int bgroup = rem >> 4;        // 0..3, 16 batches
    const int ci     = rem & 15;        // 0..15, cells [ci*16, ci*16+16)
    const int b0     = bgroup << 4;
    const int tid    = threadIdx.x;
    const int warp   = tid >> 5;        // 0..15
    const int ntile  = warp & 3;        // 16-col tile within our 64 gate-cols
    const int kq     = warp >> 2;       // k-range quarter (0..3)

    const float* wi  = dir ? wi_b  : wi_f;
    const float* Whh = dir ? Whh_b : Whh_f;

    // resident weight slice [256 k][64 cc], split to bf16 hi/mid
    for (int idx = tid; idx < 16384; idx += 512) {
        int k = idx >> 6, cc = idx & 63;
        int gc = ((cc >> 4) << 8) + (ci << 4) + (cc & 15);
        float v = __ldg(Whh + (size_t)k * GATES + gc);
        __nv_bfloat16 h = __float2bfloat16(v);
        sWh[k * RW_LD + cc] = h;
        sWm[k * RW_LD + cc] = __float2bfloat16(v - __bfloat162float(h));
    }

    // gather mapping: 32 threads per batch row, each 8 consecutive j
    const int gb = tid >> 5;            // 0..15 batch within group
    const int gj = (tid & 31) << 3;     // j0

    // cell ownership (threads 0..255): thread owns cell (cj, cb)
    const int cb = (tid >> 4) & 15;     // batch
    const int cj = tid & 15;            // cell col within our 16
    const int clen = g_len[b0 + cb];
    float cC = 0.f, hC = 0.f;

    unsigned int* ctr = &g_ctr[dir][bgroup];
    __syncthreads();

    for (int s = 0; s < TT; s++) {
        // gather h tile (coalesced: 2x LDG.128 per thread), split to bf16 planes
        {
            const float* hb = g_hbuf[dir][s & 1] + (b0 + gb) * HID + gj;
            float4 v0 = __ldcg((const float4*)hb);
            float4 v1 = __ldcg((const float4*)hb + 1);
            float vv[8] = {v0.x, v0.y, v0.z, v0.w, v1.x, v1.y, v1.z, v1.w};
            __nv_bfloat16 hh[8], mm[8];
#pragma unroll
            for (int q = 0; q < 8; q++) {
                __nv_bfloat16 h = __float2bfloat16(vv[q]);
                hh[q] = h;
                mm[q] = __float2bfloat16(vv[q] - __bfloat162float(h));
            }
            *(uint4*)(sHh + gb * RH_LD + gj) = *(uint4*)hh;
            *(uint4*)(sHm + gb * RH_LD + gj) = *(uint4*)mm;
        }
        const int t = dir ? (TT - 1 - s) : s;

        // wi loads for own cell's 4 gates (threads 0..255); consumed after mma
        float w0 = 0.f, w1 = 0.f, w2 = 0.f, w3 = 0.f;
        if (tid < 256) {
            const float* wrow = wi + ((size_t)t * NB + b0 + cb) * GATES + (ci << 4) + cj;
            w0 = __ldg(wrow + 0);
            w1 = __ldg(wrow + 256);
            w2 = __ldg(wrow + 512);
            w3 = __ldg(wrow + 768);
        }
        __syncthreads();

        // gates = h @ Whh via HMMA: warp -> n-tile ntile, k-quarter kq.
        {
            wmma::fragment<wmma::accumulator, 16, 16, 16, float> acc0, acc1;
            wmma::fill_fragment(acc0, 0.0f);
            wmma::fill_fragment(acc1, 0.0f);
#pragma unroll
            for (int q = 0; q < 2; q++) {
#pragma unroll
                for (int e = 0; e < 2; e++) {
                    int kt = (kq << 2) + (q << 1) + e;
                    wmma::fragment<wmma::matrix_a, 16, 16, 16, __nv_bfloat16, wmma::row_major> ah, am;
                    wmma::fragment<wmma::matrix_b, 16, 16, 16, __nv_bfloat16, wmma::row_major> bh, bm;
                    wmma::load_matrix_sync(ah, sHh + kt * 16, RH_LD);
                    wmma::load_matrix_sync(am, sHm + kt * 16, RH_LD);
                    wmma::load_matrix_sync(bh, sWh + (kt * 16) * RW_LD + ntile * 16, RW_LD);
                    wmma::load_matrix_sync(bm, sWm + (kt * 16) * RW_LD + ntile * 16, RW_LD);
                    if (e == 0) {
                        wmma::mma_sync(acc0, ah, bh, acc0);
                        wmma::mma_sync(acc0, ah, bm, acc0);
                        wmma::mma_sync(acc0, am, bh, acc0);
                    } else {
                        wmma::mma_sync(acc1, ah, bh, acc1);
                        wmma::mma_sync(acc1, ah, bm, acc1);
                        wmma::mma_sync(acc1, am, bh, acc1);
                    }
                }
            }
#pragma unroll
            for (int e = 0; e < acc0.num_elements; e++) acc0.x[e] += acc1.x[e];
            wmma::store_matrix_sync(sG + kq * (16 * SG_LD) + ntile * 16,
                                    acc0, SG_LD, wmma::mem_row_major);
        }
        __syncthreads();

        float ov = 0.f;
        if (tid < 256) {   // cell update: sum 4 k-quarter partials
            const float* g0 = sG + cb * SG_LD;
            const float* g1 = g0 + 16 * SG_LD;
            const float* g2 = g1 + 16 * SG_LD;
            const float* g3 = g2 + 16 * SG_LD;
            float gi = g0[cj]      + g1[cj]      + g2[cj]      + g3[cj]      + w0;
            float gf = g0[16 + cj] + g1[16 + cj] + g2[16 + cj] + g3[16 + cj] + w1;
            float go = g0[32 + cj] + g1[32 + cj] + g2[32 + cj] + g3[32 + cj] + w2;
            float gc = g0[48 + cj] + g1[48 + cj] + g2[48 + cj] + g3[48 + cj] + w3;
            float cN = sigm(gf + 1.f) * cC + sigm(gi) * tanhf(gc);
            float hN = sigm(go) * tanhf(cN);
            if (t < clen) { cC = cN; hC = hN; ov = hN; }
            __stcg(&g_hbuf[dir][(s + 1) & 1][(b0 + cb) * HID + (ci << 4) + cj], hC);
        }

        // release h stores, then overlap DRAM outbuf store with the spin window
        __syncthreads();
        if (tid == 0) atom_add_release(ctr, 1u);
        if (tid < 256)
            outbuf[((size_t)s * NB + b0 + cb) * OC + (dir << 8) + (ci << 4) + cj] = ov;
        if (tid == 0) {
            unsigned int target = (unsigned int)((s + 1) << 4);
            while (ld_acquire(ctr) < target) __nanosleep(32);
        }
        __syncthreads();
    }

    if (tid < 256) {
        hn[((size_t)dir * NB + b0 + cb) * HID + (ci << 4) + cj] = hC;
        cn[((size_t)dir * NB + b0 + cb) * HID + (ci << 4) + cj] = cC;
    }
}

// ---------------- launcher ----------------
extern "C" void kernel_launch(void* const* d_in, const int* in_sizes, int n_in,
                              void* d_out, int out_size)
{
    const float* inputs  = (const float*)d_in[0];
    const int*   lengths = (const int*)d_in[1];   // width auto-detected on device
    const float* Wih_f0 = (const float*)d_in[2];
    const float* Whh_f0 = (const float*)d_in[3];
    const float* b_f0   = (const float*)d_in[4];
    const float* Wih_b0 = (const float*)d_in[5];
    const float* Whh_b0 = (const float*)d_in[6];
    const float* b_b0   = (const float*)d_in[7];
    const float* Wih_f1 = (const float*)d_in[8];
    const float* Whh_f1 = (const float*)d_in[9];
    const float* b_f1   = (const float*)d_in[10];
    const float* Wih_b1 = (const float*)d_in[11];
    const float* Whh_b1 = (const float*)d_in[12];
    const float* b_b1   = (const float*)d_in[13];
    float* out = (float*)d_out;

    float *wi_f, *wi_b, *x1;
    __nv_bfloat16 *Ah, *Am, *Wh, *Wm;
    cudaGetSymbolAddress((void**)&wi_f, g_wi_f);
    cudaGetSymbolAddress((void**)&wi_b, g_wi_b);
    cudaGetSymbolAddress((void**)&x1,  g_x1);
    cudaGetSymbolAddress((void**)&Ah, g_Ah);
    cudaGetSymbolAddress((void**)&Am, g_Am);
    cudaGetSymbolAddress((void**)&Wh, g_Wh);
    cudaGetSymbolAddress((void**)&Wm, g_Wm);

    cudaFuncSetAttribute(lstm_layer, cudaFuncAttributeMaxDynamicSharedMemorySize, REC_SM_BYTES);
    cudaFuncSetAttribute(bf16_gemm_bias, cudaFuncAttributeMaxDynamicSharedMemorySize, GEMM_SM_BYTES);

    float* hn0 = out + (size_t)TT * NB * OC;          // hn: (4, B, H)
    float* cn0 = hn0 + 4 * NB * HID;                  // cn: (4, B, H)

    dim3 gGrid(8, 256, 2);   // N tiles x M tiles x direction

    // ---- layer 0 (slot #4 = lstm_layer for ncu) ----
    split2<<<1024, 256>>>(inputs, Ah, Am, TT * NB * IN0);                   // 1
    split2W<<<256, 256>>>(Wih_f0, Wih_b0, Wh, Wm, IN0 * GATES, lengths);    // 2 (+reset)
    bf16_gemm_bias<<<gGrid, 256, GEMM_SM_BYTES>>>(Ah, Am, Wh, Wm,           // 3
                                                  b_f0, wi_f, b_b0, wi_b, IN0);
    lstm_layer<<<128, 512, REC_SM_BYTES>>>(wi_f, wi_b, Whh_f0, Whh_b0, x1,  // 4
                                           hn0, cn0);

    // ---- layer 1 ----
    split2<<<1024, 256>>>(x1, Ah, Am, TT * NB * OC);
    split2W<<<512, 256>>>(Wih_f1, Wih_b1, Wh, Wm, OC * GATES, lengths);     // re-resets hbuf/ctr
    bf16_gemm_bias<<<gGrid, 256, GEMM_SM_BYTES>>>(Ah, Am, Wh, Wm,
                                                  b_f1, wi_f, b_b1, wi_b, OC);
    lstm_layer<<<128, 512, REC_SM_BYTES>>>(wi_f, wi_b, Whh_f1, Whh_b1, out,
                                           hn0 + 2 * NB * HID, cn0 + 2 * NB * HID);
}